// round 10
// baseline (speedup 1.0000x reference)
#include <cuda_runtime.h>
#include <cuda_bf16.h>
#include <cuda_fp16.h>
#include <cuda_fp8.h>
#include <cstdint>

// ============================================================================
// GUSC1 ISTA-net round 10: big GEMMs = bf16 main term (HMMA.16816) + fp8
// correction terms (HMMA.16832, f16 accum, scaled 2^16). 33% fewer MMA instrs
// than the 3x bf16 split at the same accuracy class.
// ============================================================================

namespace cfg {
constexpr int  BATCH = 4;
constexpr int  N     = 8192;
constexpr int  DIM   = 64;
constexpr int  HID   = 128;
constexpr int  ITERS = 8;
constexpr long ROWS  = (long)BATCH * N;   // 32768
}

// scales: term2 = (A_lo*2^14)@(X_hi*2^2), term3 = (A_hi*2^6)@(X_lo*2^10)
// both carry 2^16; epilogue multiplies corr by 2^-16.
#define SA8H 64.0f
#define SA8L 16384.0f
#define SX8H 4.0f
#define SX8L 1024.0f
#define CORR_INV (1.0f / 65536.0f)

// ---------------------------------------------------------------------------
// Scratch (device globals)
// ---------------------------------------------------------------------------
__device__ float g_sz  [cfg::BATCH * cfg::N * 128];
__device__ float g_Asz [cfg::BATCH * cfg::N * 128];
__device__ float g_t64 [cfg::BATCH * cfg::N * 64];
__device__ float g_bx  [cfg::BATCH * cfg::N * 64];
__device__ float g_y   [cfg::BATCH * cfg::N * 64];
__device__ float g_hid [cfg::BATCH * cfg::N * 128];
__device__ float g_snew[cfg::BATCH * cfg::N * 64];

__device__ __nv_bfloat16 g_Ahi[(long)cfg::N * cfg::N];
__device__ unsigned char g_Ahi8[(long)cfg::N * cfg::N];   // fp8(A_hi * 2^6)
__device__ unsigned char g_Alo8[(long)cfg::N * cfg::N];   // fp8(A_lo * 2^14)
__device__ __nv_bfloat16 g_Xhi [512L * cfg::N];           // [col, K] K-major
__device__ unsigned char g_Xhi8[512L * cfg::N];           // fp8(X_hi * 2^2)
__device__ unsigned char g_Xlo8[512L * cfg::N];           // fp8(X_lo * 2^10)

// ---------------------------------------------------------------------------
// helpers
// ---------------------------------------------------------------------------
__device__ __forceinline__ uint32_t smem_to_u32(const void* p) {
    uint32_t a;
    asm("{ .reg .u64 t; cvta.to.shared.u64 t, %1; cvt.u32.u64 %0, t; }"
        : "=r"(a) : "l"(p));
    return a;
}
__device__ __forceinline__ void cp_async16(uint32_t dst, const void* src) {
    asm volatile("cp.async.cg.shared.global [%0], [%1], 16;" :: "r"(dst), "l"(src));
}
__device__ __forceinline__ void cp_async_commit() {
    asm volatile("cp.async.commit_group;");
}
template <int NWAIT>
__device__ __forceinline__ void cp_async_wait() {
    asm volatile("cp.async.wait_group %0;" :: "n"(NWAIT));
}
__device__ __forceinline__ void ldsm_x4(uint32_t& r0, uint32_t& r1,
                                        uint32_t& r2, uint32_t& r3, uint32_t addr) {
    asm volatile("ldmatrix.sync.aligned.m8n8.x4.shared.b16 {%0,%1,%2,%3}, [%4];"
                 : "=r"(r0), "=r"(r1), "=r"(r2), "=r"(r3) : "r"(addr));
}
__device__ __forceinline__ void mma16816(float& c0, float& c1, float& c2, float& c3,
                                         uint32_t a0, uint32_t a1, uint32_t a2, uint32_t a3,
                                         uint32_t b0, uint32_t b1) {
    asm volatile("mma.sync.aligned.m16n8k16.row.col.f32.bf16.bf16.f32 "
                 "{%0,%1,%2,%3}, {%4,%5,%6,%7}, {%8,%9}, {%0,%1,%2,%3};"
                 : "+f"(c0), "+f"(c1), "+f"(c2), "+f"(c3)
                 : "r"(a0), "r"(a1), "r"(a2), "r"(a3), "r"(b0), "r"(b1));
}
// fp8 e4m3 mma, f16 accumulators (2 b32 regs hold 4 halves)
__device__ __forceinline__ void mma16832f8(uint32_t& c0, uint32_t& c1,
                                           uint32_t a0, uint32_t a1, uint32_t a2, uint32_t a3,
                                           uint32_t b0, uint32_t b1) {
    asm volatile("mma.sync.aligned.m16n8k32.row.col.f16.e4m3.e4m3.f16 "
                 "{%0,%1}, {%2,%3,%4,%5}, {%6,%7}, {%0,%1};"
                 : "+r"(c0), "+r"(c1)
                 : "r"(a0), "r"(a1), "r"(a2), "r"(a3), "r"(b0), "r"(b1));
}

// ---------------------------------------------------------------------------
// GEMM config. BM=64, BN=128, KT=64, 256 threads, 8 warps (2x4), warp 32x32,
// 2 stages x 48KB, 2 CTAs/SM (R5 shape).
// ---------------------------------------------------------------------------
namespace tg {
constexpr int K   = 8192;
constexpr int KT  = 64;
constexpr int NCH = K / KT;            // 128
constexpr int BM  = 64;
constexpr int BN  = 128;
// stage layout (bytes)
constexpr uint32_t O_AH16 = 0;         //  64 x 128B  bf16 A_hi
constexpr uint32_t O_BH16 = 8192;      // 128 x 128B  bf16 B_hi
constexpr uint32_t O_A8H  = 24576;     //  64 x  64B  fp8 A_hi'
constexpr uint32_t O_A8L  = 28672;     //  64 x  64B  fp8 A_lo'
constexpr uint32_t O_B8H  = 32768;     // 128 x  64B  fp8 B_hi'
constexpr uint32_t O_B8L  = 40960;     // 128 x  64B  fp8 B_lo'
constexpr uint32_t STG    = 49152;
constexpr uint32_t SMEM_TOTAL = 2 * STG;   // 98304 per CTA
}

// swizzled byte offset for 128B-row tiles
__device__ __forceinline__ uint32_t swz(int row, int x) {
    return (uint32_t)(row * 128 + (x ^ ((row & 7) << 4)));
}
// packed pair-row swizzle for 64B-row tiles (two logical rows per 128B row)
__device__ __forceinline__ uint32_t swz2(int r, int x) {
    const int pr = r >> 1;
    const int y  = ((r & 1) << 6) | x;
    return (uint32_t)(pr * 128 + (y ^ ((pr & 7) << 4)));
}

__global__ __launch_bounds__(256, 2) void tgemm_hmma(
    const __nv_bfloat16* __restrict__ Ahi,
    const unsigned char* __restrict__ Ahi8, const unsigned char* __restrict__ Alo8,
    const __nv_bfloat16* __restrict__ Bhi,
    const unsigned char* __restrict__ Bhi8, const unsigned char* __restrict__ Blo8,
    float* __restrict__ out, int cbShift)
{
    using namespace tg;
    extern __shared__ char smem[];
    const uint32_t sb  = smem_to_u32(smem);
    const int tid  = threadIdx.x;
    const int lane = tid & 31;
    const int wid  = tid >> 5;
    const int wm   = wid >> 2;      // 0..1
    const int wn   = wid & 3;       // 0..3
    const long m0  = (long)blockIdx.x * BM;
    const int  n0  = blockIdx.y * BN;

    // loader geometry
    const int c0r  = tid >> 3;      // 0..31  (16B chunks in 128B rows)
    const int c0s  = tid & 7;
    const int r8w  = tid >> 2;      // 0..63  (16B chunks in 64B rows)
    const int s8w  = tid & 3;

    float acc[2][4][4];
#pragma unroll
    for (int i = 0; i < 2; i++)
#pragma unroll
        for (int j = 0; j < 4; j++)
#pragma unroll
            for (int q2 = 0; q2 < 4; q2++) acc[i][j][q2] = 0.f;
    uint32_t corr[2][4][2];
#pragma unroll
    for (int i = 0; i < 2; i++)
#pragma unroll
        for (int j = 0; j < 4; j++) { corr[i][j][0] = 0u; corr[i][j][1] = 0u; }

    // ldmatrix per-lane geometry (same formulas serve bf16 and fp8 tiles)
    const int q  = lane >> 3;
    const int r8 = lane & 7;
    const int a_row_off = wm * 32 + r8 + (q & 1) * 8;   // + mi*16
    const int a_k_off   = (q >> 1) * 16;
    const int b_row_off = wn * 32 + r8 + (q >> 1) * 8;  // + ni*16
    const int b_k_off   = (q & 1) * 16;

#define LOAD_STAGE(ST, K0)                                                     \
    do {                                                                       \
        const uint32_t base_ = sb + (uint32_t)(ST) * STG;                      \
        /* bf16 A_hi: rows c0r, c0r+32 */                                      \
        {                                                                      \
            const uint32_t o0_ = swz(c0r,      c0s * 16);                      \
            const uint32_t o1_ = swz(c0r + 32, c0s * 16);                      \
            cp_async16(base_ + O_AH16 + o0_, Ahi + (m0 + c0r)      * (long)K + (K0) + c0s * 8); \
            cp_async16(base_ + O_AH16 + o1_, Ahi + (m0 + c0r + 32) * (long)K + (K0) + c0s * 8); \
        }                                                                      \
        /* bf16 B_hi: rows c0r + rr*32 */                                      \
        _Pragma("unroll")                                                      \
        for (int rr_ = 0; rr_ < 4; rr_++) {                                    \
            const int br_ = c0r + rr_ * 32;                                    \
            cp_async16(base_ + O_BH16 + swz(br_, c0s * 16),                    \
                       Bhi + ((long)n0 + br_) * K + (K0) + c0s * 8);           \
        }                                                                      \
        /* fp8 A tiles: row r8w (0..63), seg s8w */                            \
        {                                                                      \
            const uint32_t o8_ = swz2(r8w, s8w * 16);                          \
            const long ga_ = (m0 + r8w) * (long)K + (K0) + s8w * 16;           \
            cp_async16(base_ + O_A8H + o8_, Ahi8 + ga_);                       \
            cp_async16(base_ + O_A8L + o8_, Alo8 + ga_);                       \
        }                                                                      \
        /* fp8 B tiles: rows r8w, r8w+64 */                                    \
        _Pragma("unroll")                                                      \
        for (int rr_ = 0; rr_ < 2; rr_++) {                                    \
            const int br_ = r8w + rr_ * 64;                                    \
            const uint32_t o8_ = swz2(br_, s8w * 16);                          \
            const long gb_ = ((long)n0 + br_) * K + (K0) + s8w * 16;           \
            cp_async16(base_ + O_B8H + o8_, Bhi8 + gb_);                       \
            cp_async16(base_ + O_B8L + o8_, Blo8 + gb_);                       \
        }                                                                      \
        cp_async_commit();                                                     \
    } while (0)

    LOAD_STAGE(0, 0);

    for (int i = 0; i < NCH; i++) {
        if (i + 1 < NCH) {
            LOAD_STAGE((i + 1) & 1, (i + 1) * KT);
            cp_async_wait<1>();
        } else {
            cp_async_wait<0>();
        }
        __syncthreads();

        const uint32_t base = sb + (uint32_t)(i & 1) * STG;

        // ---- term 1: bf16 A_hi @ B_hi (4 k16 steps) ----
#pragma unroll
        for (int s = 0; s < 4; s++) {
            const int kb = s * 32;
            uint32_t ah[2][4], bh[2][4];
#pragma unroll
            for (int mi = 0; mi < 2; mi++) {
                const uint32_t ad = base + O_AH16 + swz(a_row_off + mi * 16, kb + a_k_off);
                ldsm_x4(ah[mi][0], ah[mi][1], ah[mi][2], ah[mi][3], ad);
            }
#pragma unroll
            for (int ni = 0; ni < 2; ni++) {
                const uint32_t bd = base + O_BH16 + swz(b_row_off + ni * 16, kb + b_k_off);
                ldsm_x4(bh[ni][0], bh[ni][1], bh[ni][2], bh[ni][3], bd);
            }
#pragma unroll
            for (int mi = 0; mi < 2; mi++)
#pragma unroll
                for (int nj = 0; nj < 4; nj++) {
                    const int g = nj >> 1, h = (nj & 1) * 2;
                    float* c = acc[mi][nj];
                    mma16816(c[0], c[1], c[2], c[3],
                             ah[mi][0], ah[mi][1], ah[mi][2], ah[mi][3],
                             bh[g][h], bh[g][h + 1]);
                }
        }

        // ---- fp8 correction terms (2 k32 steps) ----
#pragma unroll
        for (int s8 = 0; s8 < 2; s8++) {
            const int xo = s8 * 32;
            // term 2: A_lo' @ B_hi'
            {
                uint32_t a8[2][4], b8[2][4];
#pragma unroll
                for (int mi = 0; mi < 2; mi++) {
                    const uint32_t ad = base + O_A8L + swz2(a_row_off + mi * 16, xo + a_k_off);
                    ldsm_x4(a8[mi][0], a8[mi][1], a8[mi][2], a8[mi][3], ad);
                }
#pragma unroll
                for (int ni = 0; ni < 2; ni++) {
                    const uint32_t bd = base + O_B8H + swz2(b_row_off + ni * 16, xo + b_k_off);
                    ldsm_x4(b8[ni][0], b8[ni][1], b8[ni][2], b8[ni][3], bd);
                }
#pragma unroll
                for (int mi = 0; mi < 2; mi++)
#pragma unroll
                    for (int nj = 0; nj < 4; nj++) {
                        const int g = nj >> 1, h = (nj & 1) * 2;
                        mma16832f8(corr[mi][nj][0], corr[mi][nj][1],
                                   a8[mi][0], a8[mi][1], a8[mi][2], a8[mi][3],
                                   b8[g][h], b8[g][h + 1]);
                    }
            }
            // term 3: A_hi' @ B_lo'
            {
                uint32_t a8[2][4], b8[2][4];
#pragma unroll
                for (int mi = 0; mi < 2; mi++) {
                    const uint32_t ad = base + O_A8H + swz2(a_row_off + mi * 16, xo + a_k_off);
                    ldsm_x4(a8[mi][0], a8[mi][1], a8[mi][2], a8[mi][3], ad);
                }
#pragma unroll
                for (int ni = 0; ni < 2; ni++) {
                    const uint32_t bd = base + O_B8L + swz2(b_row_off + ni * 16, xo + b_k_off);
                    ldsm_x4(b8[ni][0], b8[ni][1], b8[ni][2], b8[ni][3], bd);
                }
#pragma unroll
                for (int mi = 0; mi < 2; mi++)
#pragma unroll
                    for (int nj = 0; nj < 4; nj++) {
                        const int g = nj >> 1, h = (nj & 1) * 2;
                        mma16832f8(corr[mi][nj][0], corr[mi][nj][1],
                                   a8[mi][0], a8[mi][1], a8[mi][2], a8[mi][3],
                                   b8[g][h], b8[g][h + 1]);
                    }
            }
        }
        __syncthreads();
    }

    // ---- epilogue: acc + corr * 2^-16 ----
    const int CB = 1 << cbShift;
    const int cbMask = CB - 1;
#pragma unroll
    for (int mi = 0; mi < 2; mi++) {
        const long row = m0 + wm * 32 + mi * 16 + (lane >> 2);
#pragma unroll
        for (int nj = 0; nj < 4; nj++) {
            const int g = n0 + wn * 32 + nj * 8 + 2 * (lane & 3);
            const int b = g >> cbShift;
            const int c = g & cbMask;
            const __half2 h01 = *reinterpret_cast<const __half2*>(&corr[mi][nj][0]);
            const __half2 h23 = *reinterpret_cast<const __half2*>(&corr[mi][nj][1]);
            const float v0 = acc[mi][nj][0] + __low2float(h01)  * CORR_INV;
            const float v1 = acc[mi][nj][1] + __high2float(h01) * CORR_INV;
            const float v2 = acc[mi][nj][2] + __low2float(h23)  * CORR_INV;
            const float v3 = acc[mi][nj][3] + __high2float(h23) * CORR_INV;
            float* p0 = out + ((long)b * 8192 + row) * CB + c;
            float* p1 = out + ((long)b * 8192 + row + 8) * CB + c;
            *reinterpret_cast<float2*>(p0) = make_float2(v0, v1);
            *reinterpret_cast<float2*>(p1) = make_float2(v2, v3);
        }
    }
#undef LOAD_STAGE
}

// ---------------------------------------------------------------------------
// A split: Ahi=bf16(a); Ahi8=fp8(hi*2^6); Alo8=fp8((a-hi)*2^14)
// ---------------------------------------------------------------------------
__global__ __launch_bounds__(256) void split_A_kernel(const float* __restrict__ A)
{
    const long n = (long)cfg::N * cfg::N;
    long idx = ((long)blockIdx.x * blockDim.x + threadIdx.x) * 4;
    if (idx >= n) return;
    float4 v = *reinterpret_cast<const float4*>(A + idx);
    float f[4] = {v.x, v.y, v.z, v.w};
#pragma unroll
    for (int q = 0; q < 4; q++) {
        const __nv_bfloat16 hi = __float2bfloat16(f[q]);
        const float hf = __bfloat162float(hi);
        g_Ahi[idx + q]  = hi;
        g_Ahi8[idx + q] = __nv_cvt_float_to_fp8(hf * SA8H, __NV_SATFINITE, __NV_E4M3);
        g_Alo8[idx + q] = __nv_cvt_float_to_fp8((f[q] - hf) * SA8L, __NV_SATFINITE, __NV_E4M3);
    }
}

// ---------------------------------------------------------------------------
// Split + transpose X: [B*N, CB] fp32 -> Xhi bf16, Xhi8, Xlo8 (K-major)
// ---------------------------------------------------------------------------
__global__ __launch_bounds__(256) void split_transpose_kernel(
    const float* __restrict__ X, int CB)
{
    __shared__ float tile[32][33];
    const int k0 = blockIdx.x * 32;
    const int j0 = blockIdx.y * 32;
    const int b  = j0 / CB;
    const int c0 = j0 % CB;
    const int tx = threadIdx.x, ty = threadIdx.y;

    for (int r = ty; r < 32; r += 8)
        tile[r][tx] = X[((long)b * cfg::N + k0 + r) * CB + c0 + tx];
    __syncthreads();
    for (int r = ty; r < 32; r += 8) {
        const float v = tile[tx][r];
        const __nv_bfloat16 hi = __float2bfloat16(v);
        const float hf = __bfloat162float(hi);
        const long o = (long)(j0 + r) * cfg::N + k0 + tx;
        g_Xhi[o]  = hi;
        g_Xhi8[o] = __nv_cvt_float_to_fp8(hf * SX8H, __NV_SATFINITE, __NV_E4M3);
        g_Xlo8[o] = __nv_cvt_float_to_fp8((v - hf) * SX8L, __NV_SATFINITE, __NV_E4M3);
    }
}

// ----------------------------------------------------------------------------
// fp32 FFMA GEMM for the small MLPs.
// epi: 0 none; 1 +bias,relu; 2 +bias (+addbuf); 3 +bias +addbuf then
//      soft-threshold pack into g_sz.
// ----------------------------------------------------------------------------
__global__ __launch_bounds__(256) void sgemm64(
    const float* __restrict__ Am, int lda, long strideA,
    const float* __restrict__ Bm, int ldb, long strideB,
    float*       __restrict__ Cm, int ldc, long strideC,
    int K, int epi,
    const float* __restrict__ bias,
    const float* __restrict__ addbuf, int ldadd,
    const float* __restrict__ alphaPtr)
{
    constexpr int BM = 128, BN = 64, BK = 8, TM = 8, TN = 4;
    __shared__ float As[BK][BM + 4];
    __shared__ float Bs[BK][BN + 4];

    const int  bz    = blockIdx.z;
    const int  ncol0 = blockIdx.y * BN;
    const float* Ab = Am + (long)bz * strideA;
    const float* Bb = Bm + (long)bz * strideB + ncol0;
    float*       Cb = Cm + (long)bz * strideC + ncol0;

    const long m0  = (long)blockIdx.x * BM;
    const int  tid = threadIdx.x;
    const int  tx  = tid & 15;
    const int  ty  = tid >> 4;

    const int arow = tid >> 1;
    const int acol = (tid & 1) * 4;
    const int brow = tid >> 5;
    const int bcol = (tid & 31) * 2;

    float acc[TM][TN];
#pragma unroll
    for (int i = 0; i < TM; i++)
#pragma unroll
        for (int j = 0; j < TN; j++) acc[i][j] = 0.f;

    for (int k0 = 0; k0 < K; k0 += BK) {
        float4 av = *reinterpret_cast<const float4*>(Ab + (m0 + arow) * lda + k0 + acol);
        As[acol + 0][arow] = av.x;
        As[acol + 1][arow] = av.y;
        As[acol + 2][arow] = av.z;
        As[acol + 3][arow] = av.w;
        float2 bv = *reinterpret_cast<const float2*>(Bb + (long)(k0 + brow) * ldb + bcol);
        Bs[brow][bcol]     = bv.x;
        Bs[brow][bcol + 1] = bv.y;
        __syncthreads();
#pragma unroll
        for (int kk = 0; kk < BK; kk++) {
            float a[TM], b[TN];
#pragma unroll
            for (int i = 0; i < TM; i++) a[i] = As[kk][ty * TM + i];
#pragma unroll
            for (int j = 0; j < TN; j++) b[j] = Bs[kk][tx * TN + j];
#pragma unroll
            for (int i = 0; i < TM; i++)
#pragma unroll
                for (int j = 0; j < TN; j++)
                    acc[i][j] = fmaf(a[i], b[j], acc[i][j]);
        }
        __syncthreads();
    }

    const float alpha = (epi == 3) ? alphaPtr[0] : 0.f;
#pragma unroll
    for (int i = 0; i < TM; i++) {
        const long row = m0 + ty * TM + i;
#pragma unroll
        for (int j = 0; j < TN; j++) {
            const int col = tx * TN + j;
            float v = acc[i][j];
            if (epi >= 1) v += bias[ncol0 + col];
            if (epi == 1) v = fmaxf(v, 0.f);
            if (addbuf != nullptr) v += addbuf[row * ldadd + ncol0 + col];
            if (epi == 3) {
                const float z = (v > alpha) ? (v - alpha)
                                            : ((v < -alpha) ? (v + alpha) : 0.f);
                g_sz[row * 128 + ncol0 + col]      = v;
                g_sz[row * 128 + 64 + ncol0 + col] = z;
            } else {
                Cb[row * ldc + col] = v;
            }
        }
    }
}

__global__ __launch_bounds__(256) void zero2_kernel()
{
    const long n = cfg::ROWS * 128;
    long idx = (long)blockIdx.x * blockDim.x + threadIdx.x;
    if (idx < n) {
        g_sz[idx]  = 0.f;
        g_Asz[idx] = 0.f;
    }
}

__global__ __launch_bounds__(256) void copy_s_kernel(float* __restrict__ out)
{
    const long n = cfg::ROWS * 64;
    long idx = (long)blockIdx.x * blockDim.x + threadIdx.x;
    if (idx >= n) return;
    out[idx] = g_sz[(idx >> 6) * 128 + (idx & 63)];
}

// ============================================================================
extern "C" void kernel_launch(void* const* d_in, const int* in_sizes, int n_in,
                              void* d_out, int out_size)
{
    using namespace cfg;
    const float* x_c   = (const float*)d_in[0];
    const float* A     = (const float*)d_in[1];
    const float* alpha = (const float*)d_in[2];
    const float* WA1 = (const float*)d_in[3];
    const float* bA1 = (const float*)d_in[4];
    const float* WA2 = (const float*)d_in[5];
    const float* bA2 = (const float*)d_in[6];
    const float* WB1 = (const float*)d_in[7];
    const float* bB1 = (const float*)d_in[8];
    const float* WB2 = (const float*)d_in[9];
    const float* bB2 = (const float*)d_in[10];
    const float* WD1 = (const float*)d_in[11];
    const float* bD1 = (const float*)d_in[12];
    const float* WD2 = (const float*)d_in[13];
    const float* bD2 = (const float*)d_in[14];
    const float* WE1 = (const float*)d_in[15];
    const float* bE1 = (const float*)d_in[16];
    const float* WE2 = (const float*)d_in[17];
    const float* bE2 = (const float*)d_in[18];
    float* out = (float*)d_out;

    float *sz, *Asz, *t64, *bxp, *yp, *hid, *snew;
    __nv_bfloat16 *Ahi, *Xhi;
    unsigned char *Ahi8, *Alo8, *Xhi8, *Xlo8;
    cudaGetSymbolAddress((void**)&sz,   g_sz);
    cudaGetSymbolAddress((void**)&Asz,  g_Asz);
    cudaGetSymbolAddress((void**)&t64,  g_t64);
    cudaGetSymbolAddress((void**)&bxp,  g_bx);
    cudaGetSymbolAddress((void**)&yp,   g_y);
    cudaGetSymbolAddress((void**)&hid,  g_hid);
    cudaGetSymbolAddress((void**)&snew, g_snew);
    cudaGetSymbolAddress((void**)&Ahi,  g_Ahi);
    cudaGetSymbolAddress((void**)&Ahi8, g_Ahi8);
    cudaGetSymbolAddress((void**)&Alo8, g_Alo8);
    cudaGetSymbolAddress((void**)&Xhi,  g_Xhi);
    cudaGetSymbolAddress((void**)&Xhi8, g_Xhi8);
    cudaGetSymbolAddress((void**)&Xlo8, g_Xlo8);

    cudaFuncSetAttribute(tgemm_hmma, cudaFuncAttributeMaxDynamicSharedMemorySize,
                         tg::SMEM_TOTAL);

    const dim3 blk(256);
    const dim3 tgb(256);
    const dim3 gT256(128, 2, 1);                // 256 output cols
    const dim3 gT512(128, 4, 1);                // 512 output cols
    const dim3 gM128((int)(ROWS / 128), 2, 1);
    const dim3 gM64 ((int)(ROWS / 128), 1, 1);
    const dim3 tblk(32, 8, 1);
    const dim3 gTr64 (N / 32, (BATCH * 64) / 32, 1);
    const dim3 gTr128(N / 32, (BATCH * 128) / 32, 1);

    // --- split A ---
    {
        const long n4 = ((long)N * N) / 4;
        split_A_kernel<<<(unsigned)((n4 + 255) / 256), blk>>>(A);
    }
    // --- init scratch ---
    {
        long n = ROWS * 128;
        zero2_kernel<<<(unsigned)((n + 255) / 256), blk>>>();
    }

    // --- t64 = A @ x_c ---
    split_transpose_kernel<<<gTr64, tblk>>>(x_c, 64);
    tgemm_hmma<<<gT256, tgb, tg::SMEM_TOTAL>>>(Ahi, Ahi8, Alo8, Xhi, Xhi8, Xlo8, t64, 6);
    // --- bx = mlpB(t64) ---
    sgemm64<<<gM128, blk>>>(t64, 64, 0, WB1, HID, 0, hid, HID, 0,
                            DIM, 1, bB1, nullptr, 0, nullptr);
    sgemm64<<<gM64, blk>>>(hid, HID, 0, WB2, 64, 0, bxp, 64, 0,
                           HID, 2, bB2, nullptr, 0, nullptr);

    for (int it = 0; it < ITERS; it++) {
        if (it > 0) {
            split_transpose_kernel<<<gTr128, tblk>>>(sz, 128);
            tgemm_hmma<<<gT512, tgb, tg::SMEM_TOTAL>>>(Ahi, Ahi8, Alo8, Xhi, Xhi8, Xlo8, Asz, 7);
        }
        // y = mlpA(Asz[:, 0:64]) + bx
        sgemm64<<<gM128, blk>>>(Asz, 128, 0, WA1, HID, 0, hid, HID, 0,
                                DIM, 1, bA1, nullptr, 0, nullptr);
        sgemm64<<<gM64, blk>>>(hid, HID, 0, WA2, 64, 0, yp, 64, 0,
                               HID, 2, bA2, bxp, 64, nullptr);
        // t64 = A @ y
        split_transpose_kernel<<<gTr64, tblk>>>(yp, 64);
        tgemm_hmma<<<gT256, tgb, tg::SMEM_TOTAL>>>(Ahi, Ahi8, Alo8, Xhi, Xhi8, Xlo8, t64, 6);
        // snew = mlpD(t64)
        sgemm64<<<gM128, blk>>>(t64, 64, 0, WD1, HID, 0, hid, HID, 0,
                                DIM, 1, bD1, nullptr, 0, nullptr);
        sgemm64<<<gM64, blk>>>(hid, HID, 0, WD2, 64, 0, snew, 64, 0,
                               HID, 2, bD2, nullptr, 0, nullptr);
        // s' = snew + mlpE(Asz[:, 64:128]); pack (s', soft_threshold(s')) -> sz
        sgemm64<<<gM128, blk>>>(Asz + 64, 128, 0, WE1, HID, 0, hid, HID, 0,
                                DIM, 1, bE1, nullptr, 0, nullptr);
        sgemm64<<<gM64, blk>>>(hid, HID, 0, WE2, 64, 0, snew, 64, 0,
                               HID, 3, bE2, snew, 64, alpha);
    }

    // --- out[:R*64] = mlpD(s) ; out[R*64:] = s ---
    sgemm64<<<gM128, blk>>>(sz, 128, 0, WD1, HID, 0, hid, HID, 0,
                            DIM, 1, bD1, nullptr, 0, nullptr);
    sgemm64<<<gM64, blk>>>(hid, HID, 0, WD2, 64, 0, out, 64, 0,
                           HID, 2, bD2, nullptr, 0, nullptr);
    {
        long n = ROWS * 64;
        copy_s_kernel<<<(unsigned)((n + 255) / 256), blk>>>(out + ROWS * 64);
    }
}

// round 11
// speedup vs baseline: 1.3482x; 1.3482x over previous
#include <cuda_runtime.h>
#include <cuda_bf16.h>
#include <cstdint>

// ============================================================================
// GUSC1 ISTA-net round 11: R7 GEMM (best, tensor-ceiling) + fused 2-layer
// HMMA MLP kernel whose epilogue emits the next GEMM's K-major bf16 split
// operands directly (transposes and hid round-trips deleted).
// ============================================================================

namespace cfg {
constexpr int  BATCH = 4;
constexpr int  N     = 8192;
constexpr int  ITERS = 8;
constexpr long ROWS  = (long)BATCH * N;   // 32768
}

// ---------------------------------------------------------------------------
// Scratch (device globals)
// ---------------------------------------------------------------------------
__device__ float g_Asz [cfg::BATCH * cfg::N * 128];  // A@(s|z) fp32 [R,128]
__device__ float g_t64 [cfg::BATCH * cfg::N * 64];   // A@x / A@y  fp32 [R,64]
__device__ float g_bx  [cfg::BATCH * cfg::N * 64];
__device__ float g_sn  [cfg::BATCH * cfg::N * 64];   // snew / s  fp32 [R,64]

__device__ __nv_bfloat16 g_Ahi[(long)cfg::N * cfg::N];
__device__ __nv_bfloat16 g_Alo[(long)cfg::N * cfg::N];
__device__ __nv_bfloat16 g_Yhi [256L * cfg::N];      // x_c / y  K-major
__device__ __nv_bfloat16 g_Ylo [256L * cfg::N];
__device__ __nv_bfloat16 g_SZhi[512L * cfg::N];      // (s|z)    K-major
__device__ __nv_bfloat16 g_SZlo[512L * cfg::N];

// weights, transposed+split: W1t [128 n][64 k], W2t [64 n][128 k]
__device__ __nv_bfloat16 g_W1h[4][128 * 64];
__device__ __nv_bfloat16 g_W1l[4][128 * 64];
__device__ __nv_bfloat16 g_W2h[4][64 * 128];
__device__ __nv_bfloat16 g_W2l[4][64 * 128];

// ---------------------------------------------------------------------------
// helpers
// ---------------------------------------------------------------------------
__device__ __forceinline__ uint32_t smem_to_u32(const void* p) {
    uint32_t a;
    asm("{ .reg .u64 t; cvta.to.shared.u64 t, %1; cvt.u32.u64 %0, t; }"
        : "=r"(a) : "l"(p));
    return a;
}
__device__ __forceinline__ void cp_async16(uint32_t dst, const void* src) {
    asm volatile("cp.async.cg.shared.global [%0], [%1], 16;" :: "r"(dst), "l"(src));
}
__device__ __forceinline__ void cp_async_commit() {
    asm volatile("cp.async.commit_group;");
}
template <int NWAIT>
__device__ __forceinline__ void cp_async_wait() {
    asm volatile("cp.async.wait_group %0;" :: "n"(NWAIT));
}
__device__ __forceinline__ void ldsm_x4(uint32_t& r0, uint32_t& r1,
                                        uint32_t& r2, uint32_t& r3, uint32_t addr) {
    asm volatile("ldmatrix.sync.aligned.m8n8.x4.shared.b16 {%0,%1,%2,%3}, [%4];"
                 : "=r"(r0), "=r"(r1), "=r"(r2), "=r"(r3) : "r"(addr));
}
__device__ __forceinline__ void mma16816(float& c0, float& c1, float& c2, float& c3,
                                         uint32_t a0, uint32_t a1, uint32_t a2, uint32_t a3,
                                         uint32_t b0, uint32_t b1) {
    asm volatile("mma.sync.aligned.m16n8k16.row.col.f32.bf16.bf16.f32 "
                 "{%0,%1,%2,%3}, {%4,%5,%6,%7}, {%8,%9}, {%0,%1,%2,%3};"
                 : "+f"(c0), "+f"(c1), "+f"(c2), "+f"(c3)
                 : "r"(a0), "r"(a1), "r"(a2), "r"(a3), "r"(b0), "r"(b1));
}
__device__ __forceinline__ uint32_t pack_bf16x2(float lo, float hi) {
    __nv_bfloat162 p = __floats2bfloat162_rn(lo, hi);
    return *reinterpret_cast<uint32_t*>(&p);
}

// swizzles: 128B-row tiles and 256B-row tiles
__device__ __forceinline__ uint32_t swz(int row, int x) {
    return (uint32_t)(row * 128 + (x ^ ((row & 7) << 4)));
}
__device__ __forceinline__ uint32_t swzH(int row, int x) {
    return (uint32_t)(row * 256 + (x ^ ((row & 7) << 4)));
}

// ---------------------------------------------------------------------------
// Big GEMM (exact R7 kernel): split-bf16 HMMA, BM=64/BN=128/KT=64, 256 thr,
// 2 CTAs/SM, term-major MMA order.
// ---------------------------------------------------------------------------
namespace tg {
constexpr int K   = 8192;
constexpr int KT  = 64;
constexpr int NCH = K / KT;
constexpr int BM  = 64;
constexpr int BN  = 128;
constexpr uint32_t SZ_A = 64 * 128;
constexpr uint32_t SZ_B = 128 * 128;
constexpr uint32_t STG  = 2 * SZ_A + 2 * SZ_B;   // 49152
constexpr uint32_t SMEM_TOTAL = 2 * STG;         // 98304
}

__global__ __launch_bounds__(256, 2) void tgemm_hmma(
    const __nv_bfloat16* __restrict__ Ahi, const __nv_bfloat16* __restrict__ Alo,
    const __nv_bfloat16* __restrict__ Bhi, const __nv_bfloat16* __restrict__ Blo,
    float* __restrict__ out, int cbShift)
{
    using namespace tg;
    extern __shared__ char smem[];
    const uint32_t sb  = smem_to_u32(smem);
    const int tid  = threadIdx.x;
    const int lane = tid & 31;
    const int wid  = tid >> 5;
    const int wm   = wid >> 2;
    const int wn   = wid & 3;
    const long m0  = (long)blockIdx.x * BM;
    const int  n0  = blockIdx.y * BN;

    const int c0r = tid >> 3;
    const int c0s = tid & 7;

    float acc[2][4][4];
#pragma unroll
    for (int i = 0; i < 2; i++)
#pragma unroll
        for (int j = 0; j < 4; j++)
#pragma unroll
            for (int q2 = 0; q2 < 4; q2++) acc[i][j][q2] = 0.f;

    const int q  = lane >> 3;
    const int r8 = lane & 7;
    const int a_row_off = wm * 32 + r8 + (q & 1) * 8;
    const int a_k_off   = (q >> 1) * 16;
    const int b_row_off = wn * 32 + r8 + (q >> 1) * 8;
    const int b_k_off   = (q & 1) * 16;

#define LOAD_STAGE(ST, K0)                                                     \
    do {                                                                       \
        const uint32_t base_ = sb + (uint32_t)(ST) * STG;                      \
        const uint32_t oA0_ = swz(c0r,      c0s * 16);                         \
        const uint32_t oA1_ = swz(c0r + 32, c0s * 16);                         \
        const long ga0_ = (m0 + c0r)      * (long)K + (K0) + c0s * 8;          \
        const long ga1_ = (m0 + c0r + 32) * (long)K + (K0) + c0s * 8;          \
        cp_async16(base_ + oA0_,        Ahi + ga0_);                           \
        cp_async16(base_ + oA1_,        Ahi + ga1_);                           \
        cp_async16(base_ + SZ_A + oA0_, Alo + ga0_);                           \
        cp_async16(base_ + SZ_A + oA1_, Alo + ga1_);                           \
        const uint32_t bB_ = base_ + 2 * SZ_A;                                 \
        _Pragma("unroll")                                                      \
        for (int rr_ = 0; rr_ < 4; rr_++) {                                    \
            const int brow_ = c0r + rr_ * 32;                                  \
            const uint32_t oB_ = swz(brow_, c0s * 16);                         \
            const long gb_ = ((long)n0 + brow_) * K + (K0) + c0s * 8;          \
            cp_async16(bB_ + oB_,        Bhi + gb_);                           \
            cp_async16(bB_ + SZ_B + oB_, Blo + gb_);                           \
        }                                                                      \
        cp_async_commit();                                                     \
    } while (0)

    LOAD_STAGE(0, 0);

    for (int i = 0; i < NCH; i++) {
        if (i + 1 < NCH) {
            LOAD_STAGE((i + 1) & 1, (i + 1) * KT);
            cp_async_wait<1>();
        } else {
            cp_async_wait<0>();
        }
        __syncthreads();

        const uint32_t base = sb + (uint32_t)(i & 1) * STG;
        const uint32_t aHB = base;
        const uint32_t aLB = base + SZ_A;
        const uint32_t bHB = base + 2 * SZ_A;
        const uint32_t bLB = base + 2 * SZ_A + SZ_B;

#pragma unroll
        for (int s = 0; s < 4; s++) {
            const int kb = s * 32;
            uint32_t ah[2][4], al[2][4], bh[2][4], bl[2][4];
#pragma unroll
            for (int mi = 0; mi < 2; mi++) {
                const uint32_t ad = swz(a_row_off + mi * 16, kb + a_k_off);
                ldsm_x4(ah[mi][0], ah[mi][1], ah[mi][2], ah[mi][3], aHB + ad);
                ldsm_x4(al[mi][0], al[mi][1], al[mi][2], al[mi][3], aLB + ad);
            }
#pragma unroll
            for (int ni = 0; ni < 2; ni++) {
                const uint32_t bd = swz(b_row_off + ni * 16, kb + b_k_off);
                ldsm_x4(bh[ni][0], bh[ni][1], bh[ni][2], bh[ni][3], bHB + bd);
                ldsm_x4(bl[ni][0], bl[ni][1], bl[ni][2], bl[ni][3], bLB + bd);
            }
#pragma unroll
            for (int mi = 0; mi < 2; mi++)
#pragma unroll
                for (int nj = 0; nj < 4; nj++) {
                    const int g = nj >> 1, h = (nj & 1) * 2;
                    float* c = acc[mi][nj];
                    mma16816(c[0], c[1], c[2], c[3],
                             ah[mi][0], ah[mi][1], ah[mi][2], ah[mi][3],
                             bh[g][h], bh[g][h + 1]);
                }
#pragma unroll
            for (int mi = 0; mi < 2; mi++)
#pragma unroll
                for (int nj = 0; nj < 4; nj++) {
                    const int g = nj >> 1, h = (nj & 1) * 2;
                    float* c = acc[mi][nj];
                    mma16816(c[0], c[1], c[2], c[3],
                             al[mi][0], al[mi][1], al[mi][2], al[mi][3],
                             bh[g][h], bh[g][h + 1]);
                }
#pragma unroll
            for (int mi = 0; mi < 2; mi++)
#pragma unroll
                for (int nj = 0; nj < 4; nj++) {
                    const int g = nj >> 1, h = (nj & 1) * 2;
                    float* c = acc[mi][nj];
                    mma16816(c[0], c[1], c[2], c[3],
                             ah[mi][0], ah[mi][1], ah[mi][2], ah[mi][3],
                             bl[g][h], bl[g][h + 1]);
                }
        }
        __syncthreads();
    }

    const int CB = 1 << cbShift;
    const int cbMask = CB - 1;
#pragma unroll
    for (int mi = 0; mi < 2; mi++) {
        const long row = m0 + wm * 32 + mi * 16 + (lane >> 2);
#pragma unroll
        for (int nj = 0; nj < 4; nj++) {
            const int g = n0 + wn * 32 + nj * 8 + 2 * (lane & 3);
            const int b = g >> cbShift;
            const int c = g & cbMask;
            float* p0 = out + ((long)b * 8192 + row) * CB + c;
            float* p1 = out + ((long)b * 8192 + row + 8) * CB + c;
            *reinterpret_cast<float2*>(p0) = make_float2(acc[mi][nj][0], acc[mi][nj][1]);
            *reinterpret_cast<float2*>(p1) = make_float2(acc[mi][nj][2], acc[mi][nj][3]);
        }
    }
#undef LOAD_STAGE
}

// ---------------------------------------------------------------------------
// Fused 2-layer MLP on HMMA (split-bf16). CTA = 128 rows, 256 threads.
//   GEMM1: X[128,64] @ W1t^T -> H[128,128] (+b1, relu)
//   GEMM2: H[128,128] @ W2t^T -> V[128,64] (+b2 [+add])
// modes: 0: outF=V            2: outF=V
//        1: outK=split(V) (64 cols, K-major)   [add=bx]
//        3: outF=V (=s), outK=split(s|z) (128 cols)  [add=sn]
//        4: outF=V (final out)
// ---------------------------------------------------------------------------
namespace fm {
constexpr uint32_t O_W1H = 0;        // 128 x 128B
constexpr uint32_t O_W1L = 16384;
constexpr uint32_t O_W2H = 32768;    //  64 x 256B
constexpr uint32_t O_W2L = 49152;
constexpr uint32_t O_XF  = 65536;    // 128 x 256B fp32 X
constexpr uint32_t O_XH  = 98304;    // 128 x 128B
constexpr uint32_t O_XL  = 114688;
// reuse region [65536, 131072):
constexpr uint32_t O_HH  = 65536;    // 128 x 256B
constexpr uint32_t O_HL  = 98304;
constexpr uint32_t O_T   = 65536;    // outT: hi then lo
constexpr uint32_t SMEM_TOTAL = 131072;
}

__global__ __launch_bounds__(256) void fmlp(
    const float* __restrict__ X, int ldx,
    const __nv_bfloat16* __restrict__ W1h, const __nv_bfloat16* __restrict__ W1l,
    const float* __restrict__ b1,
    const __nv_bfloat16* __restrict__ W2h, const __nv_bfloat16* __restrict__ W2l,
    const float* __restrict__ b2,
    const float* __restrict__ add,
    float* __restrict__ outF,
    __nv_bfloat16* __restrict__ outKh, __nv_bfloat16* __restrict__ outKl,
    const float* __restrict__ alphaPtr, int mode)
{
    using namespace fm;
    extern __shared__ char smem[];
    const uint32_t sb = smem_to_u32(smem);
    const int tid  = threadIdx.x;
    const int lane = tid & 31;
    const int wid  = tid >> 5;
    const long m0  = (long)blockIdx.x * 128;

    // ---- async loads: W1 hi/lo, W2 hi/lo, X fp32 ----
    {
#pragma unroll
        for (int j = 0; j < 4; j++) {              // W1: 1024 chunks each
            const int idx = tid + j * 256;
            const int row = idx >> 3, seg = idx & 7;
            const uint32_t o = swz(row, seg * 16);
            cp_async16(sb + O_W1H + o, W1h + row * 64 + seg * 8);
            cp_async16(sb + O_W1L + o, W1l + row * 64 + seg * 8);
        }
#pragma unroll
        for (int j = 0; j < 4; j++) {              // W2: 1024 chunks each
            const int idx = tid + j * 256;
            const int row = idx >> 4, seg = idx & 15;
            const uint32_t o = swzH(row, seg * 16);
            cp_async16(sb + O_W2H + o, W2h + row * 128 + seg * 8);
            cp_async16(sb + O_W2L + o, W2l + row * 128 + seg * 8);
        }
#pragma unroll
        for (int j = 0; j < 8; j++) {              // X fp32: 2048 chunks
            const int idx = tid + j * 256;
            const int row = idx >> 4, seg = idx & 15;
            cp_async16(sb + O_XF + row * 256 + seg * 16,
                       X + (m0 + row) * (long)ldx + seg * 4);
        }
        cp_async_commit();
        cp_async_wait<0>();
        __syncthreads();
    }

    // ---- convert X fp32 -> bf16 hi/lo (swizzled 128B rows) ----
#pragma unroll
    for (int j = 0; j < 16; j++) {
        const int p = tid + j * 256;               // pair index (4096 total)
        const int row = p >> 5, kp = p & 31;
        const float2 v = *reinterpret_cast<const float2*>(smem + O_XF + row * 256 + kp * 8);
        const __nv_bfloat16 h0 = __float2bfloat16(v.x);
        const __nv_bfloat16 h1 = __float2bfloat16(v.y);
        const float l0 = v.x - __bfloat162float(h0);
        const float l1 = v.y - __bfloat162float(h1);
        const uint32_t oo = swz(row, kp * 4);
        *reinterpret_cast<uint32_t*>(smem + O_XH + oo) =
            ((uint32_t)*reinterpret_cast<const uint16_t*>(&h1) << 16) |
             (uint32_t)*reinterpret_cast<const uint16_t*>(&h0);
        *reinterpret_cast<uint32_t*>(smem + O_XL + oo) = pack_bf16x2(l0, l1);
    }
    __syncthreads();

    const int q  = lane >> 3;
    const int r8 = lane & 7;

    // ---- GEMM1: warps 2m x 4n, warp tile 64x32 ----
    float acc1[4][4][4];
#pragma unroll
    for (int i = 0; i < 4; i++)
#pragma unroll
        for (int j = 0; j < 4; j++)
#pragma unroll
            for (int k = 0; k < 4; k++) acc1[i][j][k] = 0.f;
    {
        const int wm1 = wid >> 2, wn1 = wid & 3;
        const int ar = wm1 * 64 + r8 + (q & 1) * 8;
        const int ax = (q >> 1) * 16;
        const int br = wn1 * 32 + r8 + (q >> 1) * 8;
        const int bx = (q & 1) * 16;
#pragma unroll
        for (int s = 0; s < 4; s++) {
            const int kx = s * 32;
            uint32_t ah[4][4], al[4][4], bh[2][4], bl[2][4];
#pragma unroll
            for (int mi = 0; mi < 4; mi++) {
                const uint32_t ad = swz(ar + mi * 16, kx + ax);
                ldsm_x4(ah[mi][0], ah[mi][1], ah[mi][2], ah[mi][3], sb + O_XH + ad);
                ldsm_x4(al[mi][0], al[mi][1], al[mi][2], al[mi][3], sb + O_XL + ad);
            }
#pragma unroll
            for (int ni = 0; ni < 2; ni++) {
                const uint32_t bd = swz(br + ni * 16, kx + bx);
                ldsm_x4(bh[ni][0], bh[ni][1], bh[ni][2], bh[ni][3], sb + O_W1H + bd);
                ldsm_x4(bl[ni][0], bl[ni][1], bl[ni][2], bl[ni][3], sb + O_W1L + bd);
            }
#pragma unroll
            for (int mi = 0; mi < 4; mi++)
#pragma unroll
                for (int nj = 0; nj < 4; nj++) {
                    const int g = nj >> 1, h = (nj & 1) * 2;
                    float* c = acc1[mi][nj];
                    mma16816(c[0], c[1], c[2], c[3],
                             ah[mi][0], ah[mi][1], ah[mi][2], ah[mi][3],
                             bh[g][h], bh[g][h + 1]);
                    mma16816(c[0], c[1], c[2], c[3],
                             al[mi][0], al[mi][1], al[mi][2], al[mi][3],
                             bh[g][h], bh[g][h + 1]);
                    mma16816(c[0], c[1], c[2], c[3],
                             ah[mi][0], ah[mi][1], ah[mi][2], ah[mi][3],
                             bl[g][h], bl[g][h + 1]);
                }
        }
    }
    __syncthreads();   // XF/XH/XL dead; region becomes H

    // ---- +b1, relu, split, store H ----
    {
        const int wm1 = wid >> 2, wn1 = wid & 3;
#pragma unroll
        for (int mi = 0; mi < 4; mi++) {
            const int row0 = wm1 * 64 + mi * 16 + (lane >> 2);
#pragma unroll
            for (int nj = 0; nj < 4; nj++) {
                const int n = wn1 * 32 + nj * 8 + 2 * (lane & 3);
                const float bb0 = __ldg(b1 + n);
                const float bb1 = __ldg(b1 + n + 1);
                float v0 = fmaxf(acc1[mi][nj][0] + bb0, 0.f);
                float v1 = fmaxf(acc1[mi][nj][1] + bb1, 0.f);
                float v2 = fmaxf(acc1[mi][nj][2] + bb0, 0.f);
                float v3 = fmaxf(acc1[mi][nj][3] + bb1, 0.f);
                const __nv_bfloat16 h0 = __float2bfloat16(v0);
                const __nv_bfloat16 h1 = __float2bfloat16(v1);
                const __nv_bfloat16 h2 = __float2bfloat16(v2);
                const __nv_bfloat16 h3 = __float2bfloat16(v3);
                const uint32_t o0 = swzH(row0,     n * 2);
                const uint32_t o1 = swzH(row0 + 8, n * 2);
                *reinterpret_cast<uint32_t*>(smem + O_HH + o0) =
                    ((uint32_t)*reinterpret_cast<const uint16_t*>(&h1) << 16) |
                     (uint32_t)*reinterpret_cast<const uint16_t*>(&h0);
                *reinterpret_cast<uint32_t*>(smem + O_HH + o1) =
                    ((uint32_t)*reinterpret_cast<const uint16_t*>(&h3) << 16) |
                     (uint32_t)*reinterpret_cast<const uint16_t*>(&h2);
                *reinterpret_cast<uint32_t*>(smem + O_HL + o0) =
                    pack_bf16x2(v0 - __bfloat162float(h0), v1 - __bfloat162float(h1));
                *reinterpret_cast<uint32_t*>(smem + O_HL + o1) =
                    pack_bf16x2(v2 - __bfloat162float(h2), v3 - __bfloat162float(h3));
            }
        }
    }
    __syncthreads();

    // ---- GEMM2: warps 4m x 2n, warp tile 32x32 ----
    float acc2[2][4][4];
#pragma unroll
    for (int i = 0; i < 2; i++)
#pragma unroll
        for (int j = 0; j < 4; j++)
#pragma unroll
            for (int k = 0; k < 4; k++) acc2[i][j][k] = 0.f;
    const int wm2 = wid >> 1, wn2 = wid & 1;
    {
        const int ar = wm2 * 32 + r8 + (q & 1) * 8;
        const int ax = (q >> 1) * 16;
        const int br = wn2 * 32 + r8 + (q >> 1) * 8;
        const int bx = (q & 1) * 16;
#pragma unroll
        for (int s = 0; s < 8; s++) {
            const int kx = s * 32;
            uint32_t ah[2][4], al[2][4], bh[2][4], bl[2][4];
#pragma unroll
            for (int mi = 0; mi < 2; mi++) {
                const uint32_t ad = swzH(ar + mi * 16, kx + ax);
                ldsm_x4(ah[mi][0], ah[mi][1], ah[mi][2], ah[mi][3], sb + O_HH + ad);
                ldsm_x4(al[mi][0], al[mi][1], al[mi][2], al[mi][3], sb + O_HL + ad);
            }
#pragma unroll
            for (int ni = 0; ni < 2; ni++) {
                const uint32_t bd = swzH(br + ni * 16, kx + bx);
                ldsm_x4(bh[ni][0], bh[ni][1], bh[ni][2], bh[ni][3], sb + O_W2H + bd);
                ldsm_x4(bl[ni][0], bl[ni][1], bl[ni][2], bl[ni][3], sb + O_W2L + bd);
            }
#pragma unroll
            for (int mi = 0; mi < 2; mi++)
#pragma unroll
                for (int nj = 0; nj < 4; nj++) {
                    const int g = nj >> 1, h = (nj & 1) * 2;
                    float* c = acc2[mi][nj];
                    mma16816(c[0], c[1], c[2], c[3],
                             ah[mi][0], ah[mi][1], ah[mi][2], ah[mi][3],
                             bh[g][h], bh[g][h + 1]);
                    mma16816(c[0], c[1], c[2], c[3],
                             al[mi][0], al[mi][1], al[mi][2], al[mi][3],
                             bh[g][h], bh[g][h + 1]);
                    mma16816(c[0], c[1], c[2], c[3],
                             ah[mi][0], ah[mi][1], ah[mi][2], ah[mi][3],
                             bl[g][h], bl[g][h + 1]);
                }
        }
    }
    __syncthreads();   // H dead; region becomes outT

    // ---- epilogue ----
    const float alpha = (mode == 3) ? __ldg(alphaPtr) : 0.f;
    const uint32_t tSz = (mode == 3) ? 32768u : 16384u;   // per hi/lo array
#pragma unroll
    for (int mi = 0; mi < 2; mi++) {
        const int  rl0 = wm2 * 32 + mi * 16 + (lane >> 2);
#pragma unroll
        for (int nj = 0; nj < 4; nj++) {
            const int c = wn2 * 32 + nj * 8 + 2 * (lane & 3);
            const float bb0 = __ldg(b2 + c);
            const float bb1 = __ldg(b2 + c + 1);
            float v[4];
            v[0] = acc2[mi][nj][0] + bb0;
            v[1] = acc2[mi][nj][1] + bb1;
            v[2] = acc2[mi][nj][2] + bb0;
            v[3] = acc2[mi][nj][3] + bb1;
            if (add != nullptr) {
                const float2 a0 = *reinterpret_cast<const float2*>(add + (m0 + rl0) * 64 + c);
                const float2 a1 = *reinterpret_cast<const float2*>(add + (m0 + rl0 + 8) * 64 + c);
                v[0] += a0.x; v[1] += a0.y; v[2] += a1.x; v[3] += a1.y;
            }
            if (outF != nullptr) {
                *reinterpret_cast<float2*>(outF + (m0 + rl0) * 64 + c)     = make_float2(v[0], v[1]);
                *reinterpret_cast<float2*>(outF + (m0 + rl0 + 8) * 64 + c) = make_float2(v[2], v[3]);
            }
            if (mode == 1 || mode == 3) {
#pragma unroll
                for (int e = 0; e < 4; e++) {
                    const int rl = rl0 + (e >> 1) * 8;
                    const int cc = c + (e & 1);
                    const float s = v[e];
                    const __nv_bfloat16 hi = __float2bfloat16(s);
                    *reinterpret_cast<__nv_bfloat16*>(smem + O_T + cc * 256 + rl * 2) = hi;
                    *reinterpret_cast<__nv_bfloat16*>(smem + O_T + tSz + cc * 256 + rl * 2) =
                        __float2bfloat16(s - __bfloat162float(hi));
                    if (mode == 3) {
                        const float z = (s > alpha) ? (s - alpha)
                                                    : ((s < -alpha) ? (s + alpha) : 0.f);
                        const __nv_bfloat16 zh = __float2bfloat16(z);
                        *reinterpret_cast<__nv_bfloat16*>(smem + O_T + (64 + cc) * 256 + rl * 2) = zh;
                        *reinterpret_cast<__nv_bfloat16*>(smem + O_T + tSz + (64 + cc) * 256 + rl * 2) =
                            __float2bfloat16(z - __bfloat162float(zh));
                    }
                }
            }
        }
    }

    if (mode == 1 || mode == 3) {
        __syncthreads();
        const int CB = (mode == 3) ? 128 : 64;
        const long bb = m0 >> 13;           // batch
        const long k0 = m0 & 8191;
        const int total = CB * 16 * 2;      // uint4 chunks: CB rows x 16 x {hi,lo}
        for (int idx = tid; idx < total; idx += 256) {
            const int arr = idx >= CB * 16;
            const int rem = arr ? idx - CB * 16 : idx;
            const int j   = rem >> 4;
            const int s16 = rem & 15;
            const uint4 val = *reinterpret_cast<const uint4*>(
                smem + O_T + (uint32_t)arr * tSz + j * 256 + s16 * 16);
            __nv_bfloat16* dst = (arr ? outKl : outKh) +
                ((long)(bb * CB + j)) * 8192 + k0 + s16 * 8;
            *reinterpret_cast<uint4*>(dst) = val;
        }
    }
}

// ---------------------------------------------------------------------------
// Weight prep: W1 [64,128] -> W1t hi/lo [128][64]; W2 [128,64] -> W2t [64][128]
// ---------------------------------------------------------------------------
__global__ __launch_bounds__(256) void prep_w_kernel(
    const float* __restrict__ W1, const float* __restrict__ W2,
    __nv_bfloat16* __restrict__ w1h, __nv_bfloat16* __restrict__ w1l,
    __nv_bfloat16* __restrict__ w2h, __nv_bfloat16* __restrict__ w2l)
{
    const int id = blockIdx.x * 256 + threadIdx.x;
    if (id < 8192) {
        const int n = id >> 6, k = id & 63;
        const float v = W1[k * 128 + n];
        const __nv_bfloat16 h = __float2bfloat16(v);
        w1h[id] = h;
        w1l[id] = __float2bfloat16(v - __bfloat162float(h));
    } else if (id < 16384) {
        const int i2 = id - 8192;
        const int n = i2 >> 7, k = i2 & 127;
        const float v = W2[k * 64 + n];
        const __nv_bfloat16 h = __float2bfloat16(v);
        w2h[i2] = h;
        w2l[i2] = __float2bfloat16(v - __bfloat162float(h));
    }
}

// ---------------------------------------------------------------------------
__global__ __launch_bounds__(256) void split_A_kernel(const float* __restrict__ A)
{
    const long n = (long)cfg::N * cfg::N;
    long idx = ((long)blockIdx.x * blockDim.x + threadIdx.x) * 4;
    if (idx >= n) return;
    float4 v = *reinterpret_cast<const float4*>(A + idx);
    float f[4] = {v.x, v.y, v.z, v.w};
#pragma unroll
    for (int q = 0; q < 4; q++) {
        __nv_bfloat16 hi = __float2bfloat16(f[q]);
        g_Ahi[idx + q] = hi;
        g_Alo[idx + q] = __float2bfloat16(f[q] - __bfloat162float(hi));
    }
}

// split+transpose x_c -> Y buffers (CB=64)
__global__ __launch_bounds__(256) void split_transpose_kernel(
    const float* __restrict__ X,
    __nv_bfloat16* __restrict__ oh, __nv_bfloat16* __restrict__ ol)
{
    __shared__ float tile[32][33];
    const int k0 = blockIdx.x * 32;
    const int j0 = blockIdx.y * 32;
    const int b  = j0 / 64;
    const int c0 = j0 % 64;
    const int tx = threadIdx.x, ty = threadIdx.y;

    for (int r = ty; r < 32; r += 8)
        tile[r][tx] = X[((long)b * cfg::N + k0 + r) * 64 + c0 + tx];
    __syncthreads();
    for (int r = ty; r < 32; r += 8) {
        const float v = tile[tx][r];
        const __nv_bfloat16 hi = __float2bfloat16(v);
        const long o = (long)(j0 + r) * cfg::N + k0 + tx;
        oh[o] = hi;
        ol[o] = __float2bfloat16(v - __bfloat162float(hi));
    }
}

__global__ __launch_bounds__(256) void zero_asz_kernel()
{
    const long n = cfg::ROWS * 128;
    long idx = (long)blockIdx.x * blockDim.x + threadIdx.x;
    if (idx < n) g_Asz[idx] = 0.f;
}

__global__ __launch_bounds__(256) void copy_s_kernel(float* __restrict__ out)
{
    const long n = cfg::ROWS * 64;
    long idx = (long)blockIdx.x * blockDim.x + threadIdx.x;
    if (idx >= n) return;
    out[idx] = g_sn[idx];
}

// ============================================================================
extern "C" void kernel_launch(void* const* d_in, const int* in_sizes, int n_in,
                              void* d_out, int out_size)
{
    using namespace cfg;
    const float* x_c   = (const float*)d_in[0];
    const float* A     = (const float*)d_in[1];
    const float* alpha = (const float*)d_in[2];
    const float* WA1 = (const float*)d_in[3];
    const float* bA1 = (const float*)d_in[4];
    const float* WA2 = (const float*)d_in[5];
    const float* bA2 = (const float*)d_in[6];
    const float* WB1 = (const float*)d_in[7];
    const float* bB1 = (const float*)d_in[8];
    const float* WB2 = (const float*)d_in[9];
    const float* bB2 = (const float*)d_in[10];
    const float* WD1 = (const float*)d_in[11];
    const float* bD1 = (const float*)d_in[12];
    const float* WD2 = (const float*)d_in[13];
    const float* bD2 = (const float*)d_in[14];
    const float* WE1 = (const float*)d_in[15];
    const float* bE1 = (const float*)d_in[16];
    const float* WE2 = (const float*)d_in[17];
    const float* bE2 = (const float*)d_in[18];
    float* out = (float*)d_out;

    float *Asz, *t64, *bxp, *sn;
    __nv_bfloat16 *Ahi, *Alo, *Yhi, *Ylo, *SZhi, *SZlo;
    __nv_bfloat16 *W1h, *W1l, *W2h, *W2l;
    cudaGetSymbolAddress((void**)&Asz,  g_Asz);
    cudaGetSymbolAddress((void**)&t64,  g_t64);
    cudaGetSymbolAddress((void**)&bxp,  g_bx);
    cudaGetSymbolAddress((void**)&sn,   g_sn);
    cudaGetSymbolAddress((void**)&Ahi,  g_Ahi);
    cudaGetSymbolAddress((void**)&Alo,  g_Alo);
    cudaGetSymbolAddress((void**)&Yhi,  g_Yhi);
    cudaGetSymbolAddress((void**)&Ylo,  g_Ylo);
    cudaGetSymbolAddress((void**)&SZhi, g_SZhi);
    cudaGetSymbolAddress((void**)&SZlo, g_SZlo);
    cudaGetSymbolAddress((void**)&W1h,  g_W1h);
    cudaGetSymbolAddress((void**)&W1l,  g_W1l);
    cudaGetSymbolAddress((void**)&W2h,  g_W2h);
    cudaGetSymbolAddress((void**)&W2l,  g_W2l);

    cudaFuncSetAttribute(tgemm_hmma, cudaFuncAttributeMaxDynamicSharedMemorySize,
                         tg::SMEM_TOTAL);
    cudaFuncSetAttribute(fmlp, cudaFuncAttributeMaxDynamicSharedMemorySize,
                         fm::SMEM_TOTAL);

    // weight slot offsets (A=0, B=1, D=2, E=3)
    auto w1h = [&](int i) { return W1h + (long)i * 128 * 64; };
    auto w1l = [&](int i) { return W1l + (long)i * 128 * 64; };
    auto w2h = [&](int i) { return W2h + (long)i * 64 * 128; };
    auto w2l = [&](int i) { return W2l + (long)i * 64 * 128; };

    const dim3 blk(256);
    const dim3 tgb(256);
    const dim3 gT256(128, 2, 1);
    const dim3 gT512(128, 4, 1);
    const dim3 gF((unsigned)(ROWS / 128), 1, 1);
    const dim3 tblk(32, 8, 1);
    const dim3 gTr64(N / 32, (BATCH * 64) / 32, 1);

    // --- one-time prep ---
    {
        const long n4 = ((long)N * N) / 4;
        split_A_kernel<<<(unsigned)((n4 + 255) / 256), blk>>>(A);
    }
    prep_w_kernel<<<64, blk>>>(WA1, WA2, w1h(0), w1l(0), w2h(0), w2l(0));
    prep_w_kernel<<<64, blk>>>(WB1, WB2, w1h(1), w1l(1), w2h(1), w2l(1));
    prep_w_kernel<<<64, blk>>>(WD1, WD2, w1h(2), w1l(2), w2h(2), w2l(2));
    prep_w_kernel<<<64, blk>>>(WE1, WE2, w1h(3), w1l(3), w2h(3), w2l(3));
    {
        long n = ROWS * 128;
        zero_asz_kernel<<<(unsigned)((n + 255) / 256), blk>>>();
    }

    // --- t64 = A @ x_c ---
    split_transpose_kernel<<<gTr64, tblk>>>(x_c, Yhi, Ylo);
    tgemm_hmma<<<gT256, tgb, tg::SMEM_TOTAL>>>(Ahi, Alo, Yhi, Ylo, t64, 6);
    // --- bx = mlpB(t64) ---
    fmlp<<<gF, blk, fm::SMEM_TOTAL>>>(t64, 64, w1h(1), w1l(1), bB1,
                                      w2h(1), w2l(1), bB2,
                                      nullptr, bxp, nullptr, nullptr, nullptr, 0);

    for (int it = 0; it < ITERS; it++) {
        if (it > 0) {
            tgemm_hmma<<<gT512, tgb, tg::SMEM_TOTAL>>>(Ahi, Alo, SZhi, SZlo, Asz, 7);
        }
        // y = mlpA(Asz[:, :64]) + bx  -> Y (K-major split)
        fmlp<<<gF, blk, fm::SMEM_TOTAL>>>(Asz, 128, w1h(0), w1l(0), bA1,
                                          w2h(0), w2l(0), bA2,
                                          bxp, nullptr, Yhi, Ylo, nullptr, 1);
        // t64 = A @ y
        tgemm_hmma<<<gT256, tgb, tg::SMEM_TOTAL>>>(Ahi, Alo, Yhi, Ylo, t64, 6);
        // sn = mlpD(t64)
        fmlp<<<gF, blk, fm::SMEM_TOTAL>>>(t64, 64, w1h(2), w1l(2), bD1,
                                          w2h(2), w2l(2), bD2,
                                          nullptr, sn, nullptr, nullptr, nullptr, 2);
        // s = sn + mlpE(Asz[:, 64:]); z = soft(s) -> SZ (K-major split), s -> sn
        fmlp<<<gF, blk, fm::SMEM_TOTAL>>>(Asz + 64, 128, w1h(3), w1l(3), bE1,
                                          w2h(3), w2l(3), bE2,
                                          sn, sn, SZhi, SZlo, alpha, 3);
    }

    // --- out[:R*64] = mlpD(s) ; out[R*64:] = s ---
    fmlp<<<gF, blk, fm::SMEM_TOTAL>>>(sn, 64, w1h(2), w1l(2), bD1,
                                      w2h(2), w2l(2), bD2,
                                      nullptr, out, nullptr, nullptr, nullptr, 4);
    {
        long n = ROWS * 64;
        copy_s_kernel<<<(unsigned)((n + 255) / 256), blk>>>(out + ROWS * 64);
    }
}